// round 6
// baseline (speedup 1.0000x reference)
#include <cuda_runtime.h>

#define HW   16384      // 128*128
#define NPIX 32768      // B * HW
#define NCLS 35

// -------- device scratch (no allocs allowed) --------
__device__ int   d_cnt[NCLS];
__device__ int   d_prefix[NCLS + 1];
__device__ int   d_clist[NCLS * NPIX];     // 4.6 MB
__device__ float d_xt[NPIX * 64];          // x' pixel-major, 8.4 MB
__device__ float d_ysc[NPIX * 64];         // y  pixel-major, 8.4 MB
__device__ float d_sum[128];
__device__ float d_sq[128];

// -------- packed f32x2 helpers (Blackwell FFMA2 — only via PTX) --------
__device__ __forceinline__ unsigned long long ffma2(unsigned long long a,
                                                    unsigned long long b,
                                                    unsigned long long c) {
    unsigned long long d;
    asm("fma.rn.f32x2 %0, %1, %2, %3;" : "=l"(d) : "l"(a), "l"(b), "l"(c));
    return d;
}
__device__ __forceinline__ unsigned long long addf2(unsigned long long a,
                                                    unsigned long long b) {
    unsigned long long d;
    asm("add.rn.f32x2 %0, %1, %2;" : "=l"(d) : "l"(a), "l"(b));
    return d;
}
__device__ __forceinline__ unsigned long long bcast2(float x) {
    unsigned long long d;
    unsigned xi = __float_as_uint(x);
    asm("mov.b64 %0, {%1, %1};" : "=l"(d) : "r"(xi));
    return d;
}
__device__ __forceinline__ float2 unpk(unsigned long long v) {
    float lo, hi;
    asm("mov.b64 {%0, %1}, %2;" : "=f"(lo), "=f"(hi) : "l"(v));
    return make_float2(lo, hi);
}

// -------- zero counters + moments (graph-replay safe) --------
__global__ void k_init() {
    int t = threadIdx.x;
    if (t < NCLS) d_cnt[t] = 0;
    if (t < 128) { d_sum[t] = 0.f; d_sq[t] = 0.f; }
}

// -------- kA: pos-scalar + argmax routing + transpose x' --------
__global__ void kA(const float* __restrict__ x, const float* __restrict__ layout,
                   const float* __restrict__ pr, const float* __restrict__ conv_w,
                   const float* __restrict__ conv_b, const float* __restrict__ pl) {
    __shared__ float tile[128 * 65];
    int t  = threadIdx.x;
    int p  = blockIdx.x * 128 + t;          // one pixel per thread
    int b  = p >> 14;
    int hw = p & (HW - 1);
    int i  = hw >> 7;      // row
    int j  = hw & 127;     // col

    float px = (float)i * (2.0f / 128.0f) - 1.0f;
    float py = (float)j * (2.0f / 128.0f) - 1.0f;
    float pl0 = pl[hw], pl1 = pl[HW + hw];
    const float* prb = pr + b * 2 * HW;
    float pr0 = prb[hw], pr1 = prb[HW + hw];
    const float A23 = 2.0943951023931953f;   // 2*pi/3
    float ax = A23 * (float)(j % 3);
    float ay = A23 * (float)(i % 3);
    float s = px * conv_w[0] + py * conv_w[1] + pl0 * conv_w[2] + pl1 * conv_w[3]
            + pr0 * conv_w[4] + pr1 * conv_w[5]
            + cosf(ax) * conv_w[6] + sinf(ax) * conv_w[7]
            + cosf(ay) * conv_w[8] + sinf(ay) * conv_w[9] + conv_b[0];

    // argmax over 35 layout channels (first-max on ties: strict >)
    const float* lb = layout + (size_t)b * NCLS * HW + hw;
    float best = lb[0];
    int arg = 0;
    #pragma unroll
    for (int k = 1; k < NCLS; k++) {
        float v = lb[(size_t)k * HW];
        if (v > best) { best = v; arg = k; }
    }
    int slot = atomicAdd(&d_cnt[arg], 1);
    d_clist[arg * NPIX + slot] = p;

    // transpose x' = x + s  ->  xt[pixel][64]
    const float* xb = x + (size_t)b * 64 * HW + hw;
    #pragma unroll 8
    for (int c = 0; c < 64; c++) tile[t * 65 + c] = xb[(size_t)c * HW] + s;
    __syncthreads();

    int p0 = blockIdx.x * 128;
    #pragma unroll
    for (int r = 0; r < 16; r++) {
        int lin = r * 128 + t;
        int pp  = lin >> 4;
        int c4  = (lin & 15) << 2;
        float4 v;
        v.x = tile[pp * 65 + c4 + 0];
        v.y = tile[pp * 65 + c4 + 1];
        v.z = tile[pp * 65 + c4 + 2];
        v.w = tile[pp * 65 + c4 + 3];
        *(float4*)&d_xt[(size_t)(p0 + pp) * 64 + c4] = v;
    }
}

// -------- kA2: prefix of per-class block counts (128-pixel chunks) --------
__global__ void kA2() {
    if (threadIdx.x == 0) {
        int acc = 0;
        for (int k = 0; k < NCLS; k++) {
            d_prefix[k] = acc;
            acc += (d_cnt[k] + 127) >> 7;
        }
        d_prefix[NCLS] = acc;
    }
}

// -------- kB: grouped GEMM, 128px/block, 8x8 thread tile, f32x2 --------
__global__ void __launch_bounds__(128, 2)
kB(const float* __restrict__ Wt, const float* __restrict__ bt) {
    __shared__ float Wsm[64 * 64];     // 16KB; reused as reduction buffer after GEMM
    __shared__ float xs[128 * 64];     // 32KB, pixel-major, xor-swizzled
    __shared__ float bsm[64];
    __shared__ int   pixs[128];
    __shared__ int   skc[2];

    int t   = threadIdx.x;
    int bid = blockIdx.x;
    if (bid >= d_prefix[NCLS]) return;

    if (t == 0) {
        int k = 0;
        while (d_prefix[k + 1] <= bid) k++;
        skc[0] = k;
        skc[1] = bid - d_prefix[k];
    }
    __syncthreads();
    int k    = skc[0];
    int base = skc[1] << 7;
    int n    = min(128, d_cnt[k] - base);

    // load expert matrix (16KB), bias, pixel list
    const float4* Wk4  = (const float4*)(Wt + (size_t)k * 4096);
    float4*       Wsm4 = (float4*)Wsm;
    #pragma unroll
    for (int r = 0; r < 8; r++) Wsm4[r * 128 + t] = Wk4[r * 128 + t];
    if (t < 64) bsm[t] = bt[k * 64 + t];
    pixs[t] = (t < n) ? d_clist[k * NPIX + base + t] : -1;
    __syncthreads();

    // gather x' rows, xor-swizzled by pixel-group to avoid bank conflicts
    float4* xs4 = (float4*)xs;
    #pragma unroll
    for (int r = 0; r < 16; r++) {
        int lin = r * 128 + t;
        int pp  = lin >> 4;
        int c4  = lin & 15;
        int pix = pixs[pp];
        float4 v = make_float4(0.f, 0.f, 0.f, 0.f);
        if (pix >= 0) v = ((const float4*)d_xt)[(size_t)pix * 16 + c4];
        xs4[pp * 16 + (c4 ^ ((pp >> 3) & 3))] = v;
    }
    __syncthreads();

    int og  = (t & 7) << 3;     // 8 outputs = 4 f32x2 pairs
    int pg  = (t >> 3) << 3;    // 8 pixels
    int psw = (pg >> 3) & 3;    // swizzle key (same for all 8 pixels of group)

    // acc init = bias (free epilogue add)
    unsigned long long bp[4];
    #pragma unroll
    for (int op = 0; op < 4; op++)
        bp[op] = *(const unsigned long long*)&bsm[og + 2 * op];
    unsigned long long acc[8][4];
    #pragma unroll
    for (int pp = 0; pp < 8; pp++)
        #pragma unroll
        for (int op = 0; op < 4; op++) acc[pp][op] = bp[op];

    #pragma unroll 4
    for (int c4 = 0; c4 < 16; c4++) {
        unsigned long long w[4][4];
        #pragma unroll
        for (int kk = 0; kk < 4; kk++) {
            const ulonglong2* wrow = (const ulonglong2*)&Wsm[(c4 * 4 + kk) * 64 + og];
            ulonglong2 wa = wrow[0];
            ulonglong2 wb = wrow[1];
            w[kk][0] = wa.x; w[kk][1] = wa.y; w[kk][2] = wb.x; w[kk][3] = wb.y;
        }
        int slot = c4 ^ psw;
        #pragma unroll
        for (int pp = 0; pp < 8; pp++) {
            float4 xv = xs4[(pg + pp) * 16 + slot];
            unsigned long long x0 = bcast2(xv.x);
            unsigned long long x1 = bcast2(xv.y);
            unsigned long long x2 = bcast2(xv.z);
            unsigned long long x3 = bcast2(xv.w);
            #pragma unroll
            for (int op = 0; op < 4; op++) {
                unsigned long long a = acc[pp][op];
                a = ffma2(x0, w[0][op], a);
                a = ffma2(x1, w[1][op], a);
                a = ffma2(x2, w[2][op], a);
                a = ffma2(x3, w[3][op], a);
                acc[pp][op] = a;
            }
        }
    }

    __syncthreads();   // Wsm reads done; safe to alias as reduction buffer

    // write y + accumulate per-(batch,output) moments as f32x2
    unsigned long long s0[4] = {0,0,0,0}, q0[4] = {0,0,0,0};
    unsigned long long s1[4] = {0,0,0,0}, q1[4] = {0,0,0,0};
    #pragma unroll
    for (int pp = 0; pp < 8; pp++) {
        int pix = pixs[pg + pp];
        if (pix >= 0) {
            float2 y0 = unpk(acc[pp][0]);
            float2 y1 = unpk(acc[pp][1]);
            float2 y2 = unpk(acc[pp][2]);
            float2 y3 = unpk(acc[pp][3]);
            float4* dst = (float4*)&d_ysc[(size_t)pix * 64 + og];
            dst[0] = make_float4(y0.x, y0.y, y1.x, y1.y);
            dst[1] = make_float4(y2.x, y2.y, y3.x, y3.y);
            if (pix < HW) {
                #pragma unroll
                for (int op = 0; op < 4; op++) {
                    s0[op] = addf2(s0[op], acc[pp][op]);
                    q0[op] = ffma2(acc[pp][op], acc[pp][op], q0[op]);
                }
            } else {
                #pragma unroll
                for (int op = 0; op < 4; op++) {
                    s1[op] = addf2(s1[op], acc[pp][op]);
                    q1[op] = ffma2(acc[pp][op], acc[pp][op], q1[op]);
                }
            }
        }
    }

    // reduce over the 4 pixel-groups sharing this og within each warp
    #pragma unroll
    for (int op = 0; op < 4; op++) {
        s0[op] = addf2(s0[op], __shfl_xor_sync(0xffffffffu, s0[op], 8));
        q0[op] = addf2(q0[op], __shfl_xor_sync(0xffffffffu, q0[op], 8));
        s1[op] = addf2(s1[op], __shfl_xor_sync(0xffffffffu, s1[op], 8));
        q1[op] = addf2(q1[op], __shfl_xor_sync(0xffffffffu, q1[op], 8));
        s0[op] = addf2(s0[op], __shfl_xor_sync(0xffffffffu, s0[op], 16));
        q0[op] = addf2(q0[op], __shfl_xor_sync(0xffffffffu, q0[op], 16));
        s1[op] = addf2(s1[op], __shfl_xor_sync(0xffffffffu, s1[op], 16));
        q1[op] = addf2(q1[op], __shfl_xor_sync(0xffffffffu, q1[op], 16));
    }

    float* red = Wsm;                      // 4 warps x 256 floats = 4KB
    int w = t >> 5;
    if ((t & 31) < 8) {
        float* rr = &red[w * 256 + (t & 7) * 32];
        #pragma unroll
        for (int op = 0; op < 4; op++) {
            float2 v;
            v = unpk(s0[op]); rr[0  + 2*op] = v.x; rr[1  + 2*op] = v.y;
            v = unpk(q0[op]); rr[8  + 2*op] = v.x; rr[9  + 2*op] = v.y;
            v = unpk(s1[op]); rr[16 + 2*op] = v.x; rr[17 + 2*op] = v.y;
            v = unpk(q1[op]); rr[24 + 2*op] = v.x; rr[25 + 2*op] = v.y;
        }
    }
    __syncthreads();

    #pragma unroll
    for (int r = 0; r < 2; r++) {
        int ss = r * 128 + t;
        float v = red[ss] + red[256 + ss] + red[512 + ss] + red[768 + ss];
        int lane_og = ss >> 5;
        int idx     = ss & 31;
        int o    = (lane_og << 3) + (idx & 7);
        int bsel = (idx >> 4) & 1;
        int isq  = (idx >> 3) & 1;
        int chan = bsel * 64 + o;
        if (isq) atomicAdd(&d_sq[chan], v);
        else     atomicAdd(&d_sum[chan], v);
    }
}

// -------- kC: instance norm + leaky + transpose to (B,C,H,W) --------
__global__ void kC(float* __restrict__ out) {
    __shared__ float tile[8][32][33];
    int t = threadIdx.x;
    int w = t >> 5, lane = t & 31;
    int p0    = blockIdx.x * 128;          // 128 pixels per block (single batch)
    int b     = p0 >> 14;
    int hw0   = p0 & (HW - 1);
    int c0    = (w & 1) * 32;
    int pbase = (w >> 1) * 32;

    int chan   = b * 64 + c0 + lane;
    float mean = d_sum[chan] * (1.0f / 16384.0f);
    float var  = d_sq[chan] * (1.0f / 16384.0f) - mean * mean;
    float rstd = rsqrtf(var + 1e-5f);

    #pragma unroll
    for (int r = 0; r < 32; r++) {
        float v = d_ysc[(size_t)(p0 + pbase + r) * 64 + c0 + lane];
        v = (v - mean) * rstd;
        v = v >= 0.f ? v : 0.01f * v;
        tile[w][r][lane] = v;
    }
    __syncwarp();
    #pragma unroll
    for (int r = 0; r < 32; r++) {
        out[(size_t)(b * 64 + c0 + r) * HW + hw0 + pbase + lane] = tile[w][lane][r];
    }
}

extern "C" void kernel_launch(void* const* d_in, const int* in_sizes, int n_in,
                              void* d_out, int out_size) {
    const float* x      = (const float*)d_in[0];
    const float* layout = (const float*)d_in[1];
    const float* pr     = (const float*)d_in[2];
    const float* conv_w = (const float*)d_in[3];
    const float* conv_b = (const float*)d_in[4];
    const float* Wt     = (const float*)d_in[5];
    const float* bt     = (const float*)d_in[6];
    const float* pl     = (const float*)d_in[7];
    float* out = (float*)d_out;

    k_init<<<1, 128>>>();
    kA<<<256, 128>>>(x, layout, pr, conv_w, conv_b, pl);
    kA2<<<1, 32>>>();
    kB<<<291, 128>>>(Wt, bt);   // 291 >= max total (class,128-chunk) blocks
    kC<<<256, 256>>>(out);
}

// round 7
// speedup vs baseline: 1.1050x; 1.1050x over previous
#include <cuda_runtime.h>

#define HW   16384      // 128*128
#define NPIX 32768      // B * HW
#define NCLS 35

// -------- device scratch (no allocs allowed) --------
__device__ int   d_cnt[NCLS];              // zero-init at load; re-zeroed by kC
__device__ int   d_prefix[NCLS + 1];
__device__ int   d_clist[NCLS * NPIX];     // 4.6 MB
__device__ float d_xt[NPIX * 64];          // x' pixel-major, 8.4 MB
__device__ float d_ysc[NPIX * 64];         // y  pixel-major, 8.4 MB
__device__ float d_sum[128];
__device__ float d_sq[128];

// -------- packed f32x2 helpers (Blackwell FFMA2 — only via PTX) --------
__device__ __forceinline__ unsigned long long ffma2(unsigned long long a,
                                                    unsigned long long b,
                                                    unsigned long long c) {
    unsigned long long d;
    asm("fma.rn.f32x2 %0, %1, %2, %3;" : "=l"(d) : "l"(a), "l"(b), "l"(c));
    return d;
}
__device__ __forceinline__ unsigned long long addf2(unsigned long long a,
                                                    unsigned long long b) {
    unsigned long long d;
    asm("add.rn.f32x2 %0, %1, %2;" : "=l"(d) : "l"(a), "l"(b));
    return d;
}
__device__ __forceinline__ unsigned long long bcast2(float x) {
    unsigned long long d;
    unsigned xi = __float_as_uint(x);
    asm("mov.b64 %0, {%1, %1};" : "=l"(d) : "r"(xi));
    return d;
}
__device__ __forceinline__ float2 unpk(unsigned long long v) {
    float lo, hi;
    asm("mov.b64 {%0, %1}, %2;" : "=f"(lo), "=f"(hi) : "l"(v));
    return make_float2(lo, hi);
}

// -------- kA: pos-scalar + argmax routing + transpose x' (+ zero moments) ----
__global__ void kA(const float* __restrict__ x, const float* __restrict__ layout,
                   const float* __restrict__ pr, const float* __restrict__ conv_w,
                   const float* __restrict__ conv_b, const float* __restrict__ pl) {
    __shared__ float tile[128 * 65];
    int t  = threadIdx.x;
    if (blockIdx.x == 0) { d_sum[t] = 0.f; d_sq[t] = 0.f; }   // before kB's atomics

    int p  = blockIdx.x * 128 + t;          // one pixel per thread
    int b  = p >> 14;
    int hw = p & (HW - 1);
    int i  = hw >> 7;      // row
    int j  = hw & 127;     // col

    float px = (float)i * (2.0f / 128.0f) - 1.0f;
    float py = (float)j * (2.0f / 128.0f) - 1.0f;
    float pl0 = pl[hw], pl1 = pl[HW + hw];
    const float* prb = pr + b * 2 * HW;
    float pr0 = prb[hw], pr1 = prb[HW + hw];
    const float A23 = 2.0943951023931953f;   // 2*pi/3
    float ax = A23 * (float)(j % 3);
    float ay = A23 * (float)(i % 3);
    float s = px * conv_w[0] + py * conv_w[1] + pl0 * conv_w[2] + pl1 * conv_w[3]
            + pr0 * conv_w[4] + pr1 * conv_w[5]
            + cosf(ax) * conv_w[6] + sinf(ax) * conv_w[7]
            + cosf(ay) * conv_w[8] + sinf(ay) * conv_w[9] + conv_b[0];

    // argmax over 35 layout channels (first-max on ties: strict >)
    const float* lb = layout + (size_t)b * NCLS * HW + hw;
    float best = lb[0];
    int arg = 0;
    #pragma unroll
    for (int k = 1; k < NCLS; k++) {
        float v = lb[(size_t)k * HW];
        if (v > best) { best = v; arg = k; }
    }
    int slot = atomicAdd(&d_cnt[arg], 1);
    d_clist[arg * NPIX + slot] = p;

    // transpose x' = x + s  ->  xt[pixel][64]
    const float* xb = x + (size_t)b * 64 * HW + hw;
    #pragma unroll 8
    for (int c = 0; c < 64; c++) tile[t * 65 + c] = xb[(size_t)c * HW] + s;
    __syncthreads();

    int p0 = blockIdx.x * 128;
    #pragma unroll
    for (int r = 0; r < 16; r++) {
        int lin = r * 128 + t;
        int pp  = lin >> 4;
        int c4  = (lin & 15) << 2;
        float4 v;
        v.x = tile[pp * 65 + c4 + 0];
        v.y = tile[pp * 65 + c4 + 1];
        v.z = tile[pp * 65 + c4 + 2];
        v.w = tile[pp * 65 + c4 + 3];
        *(float4*)&d_xt[(size_t)(p0 + pp) * 64 + c4] = v;
    }
}

// -------- kA2: parallel scan of per-class block counts (128-px chunks) ------
__global__ void kA2() {
    __shared__ int sc[64];
    int t = threadIdx.x;    // 64 threads
    int v = (t < NCLS) ? ((d_cnt[t] + 127) >> 7) : 0;
    sc[t] = v;
    __syncthreads();
    #pragma unroll
    for (int off = 1; off < 64; off <<= 1) {
        int u = (t >= off) ? sc[t - off] : 0;
        __syncthreads();
        sc[t] += u;
        __syncthreads();
    }
    if (t == 0) d_prefix[0] = 0;
    if (t < NCLS) d_prefix[t + 1] = sc[t];   // inclusive -> prefix[k+1]
}

// -------- kB: grouped GEMM, 128px/block, 256 thr, 4x8 f32x2 tile ------------
__global__ void __launch_bounds__(256, 2)
kB(const float* __restrict__ Wt, const float* __restrict__ bt) {
    __shared__ float Wsm[64 * 64];     // 16KB; aliased as reduction buf after GEMM
    __shared__ float xs[128 * 64];     // 32KB, pixel-major, xor-swizzled

    int t   = threadIdx.x;
    int bid = blockIdx.x;
    if (bid >= d_prefix[NCLS]) return;

    // per-thread binary search: largest k with prefix[k] <= bid (uniform)
    int lo = 0, hi = NCLS;
    #pragma unroll
    for (int it = 0; it < 6; it++) {
        int mid = (lo + hi) >> 1;
        if (d_prefix[mid] <= bid) lo = mid; else hi = mid;
    }
    int k    = lo;
    int base = (bid - d_prefix[k]) << 7;
    int n    = min(128, d_cnt[k] - base);
    const int* clist = d_clist + k * NPIX + base;

    // load expert matrix (16KB)
    const float4* Wk4  = (const float4*)(Wt + (size_t)k * 4096);
    float4*       Wsm4 = (float4*)Wsm;
    #pragma unroll
    for (int r = 0; r < 4; r++) Wsm4[r * 256 + t] = Wk4[r * 256 + t];

    // gather x' rows, xor-swizzled by pixel (key = (pix>>2)&3)
    float4* xs4 = (float4*)xs;
    #pragma unroll
    for (int r = 0; r < 8; r++) {
        int lin = r * 256 + t;
        int pp  = lin >> 4;
        int c4  = lin & 15;
        float4 v = make_float4(0.f, 0.f, 0.f, 0.f);
        if (pp < n) {
            int pix = clist[pp];
            v = ((const float4*)d_xt)[(size_t)pix * 16 + c4];
        }
        xs4[pp * 16 + (c4 ^ ((pp >> 2) & 3))] = v;
    }
    __syncthreads();

    int og8 = (t & 7) << 3;     // 8 outputs = 4 f32x2 pairs
    int pg4 = (t >> 3) << 2;    // 4 pixels
    int key = (t >> 3) & 3;     // swizzle key for this pixel quad

    // acc init = bias (LDG from bt, L2-hot)
    unsigned long long acc[4][4];
    {
        const unsigned long long* bb =
            (const unsigned long long*)(bt + k * 64 + og8);
        unsigned long long b0 = bb[0], b1 = bb[1], b2 = bb[2], b3 = bb[3];
        #pragma unroll
        for (int pp = 0; pp < 4; pp++) {
            acc[pp][0] = b0; acc[pp][1] = b1; acc[pp][2] = b2; acc[pp][3] = b3;
        }
    }

    #pragma unroll 4
    for (int c4 = 0; c4 < 16; c4++) {
        unsigned long long w[4][4];
        #pragma unroll
        for (int kk = 0; kk < 4; kk++) {
            const ulonglong2* wrow = (const ulonglong2*)&Wsm[(c4 * 4 + kk) * 64 + og8];
            ulonglong2 wa = wrow[0];
            ulonglong2 wb = wrow[1];
            w[kk][0] = wa.x; w[kk][1] = wa.y; w[kk][2] = wb.x; w[kk][3] = wb.y;
        }
        int slot = c4 ^ key;
        #pragma unroll
        for (int pp = 0; pp < 4; pp++) {
            float4 xv = xs4[(pg4 + pp) * 16 + slot];
            unsigned long long x0 = bcast2(xv.x);
            unsigned long long x1 = bcast2(xv.y);
            unsigned long long x2 = bcast2(xv.z);
            unsigned long long x3 = bcast2(xv.w);
            #pragma unroll
            for (int op = 0; op < 4; op++) {
                unsigned long long a = acc[pp][op];
                a = ffma2(x0, w[0][op], a);
                a = ffma2(x1, w[1][op], a);
                a = ffma2(x2, w[2][op], a);
                a = ffma2(x3, w[3][op], a);
                acc[pp][op] = a;
            }
        }
    }

    __syncthreads();   // Wsm reads done; safe to alias as reduction buffer

    // write y + accumulate per-(batch,output) moments as f32x2
    unsigned long long s0[4] = {0,0,0,0}, q0[4] = {0,0,0,0};
    unsigned long long s1[4] = {0,0,0,0}, q1[4] = {0,0,0,0};
    #pragma unroll
    for (int pp = 0; pp < 4; pp++) {
        if (pg4 + pp < n) {
            int pix = clist[pg4 + pp];
            float2 y0 = unpk(acc[pp][0]);
            float2 y1 = unpk(acc[pp][1]);
            float2 y2 = unpk(acc[pp][2]);
            float2 y3 = unpk(acc[pp][3]);
            float4* dst = (float4*)&d_ysc[(size_t)pix * 64 + og8];
            dst[0] = make_float4(y0.x, y0.y, y1.x, y1.y);
            dst[1] = make_float4(y2.x, y2.y, y3.x, y3.y);
            if (pix < HW) {
                #pragma unroll
                for (int op = 0; op < 4; op++) {
                    s0[op] = addf2(s0[op], acc[pp][op]);
                    q0[op] = ffma2(acc[pp][op], acc[pp][op], q0[op]);
                }
            } else {
                #pragma unroll
                for (int op = 0; op < 4; op++) {
                    s1[op] = addf2(s1[op], acc[pp][op]);
                    q1[op] = ffma2(acc[pp][op], acc[pp][op], q1[op]);
                }
            }
        }
    }

    // lanes {og, og+8, og+16, og+24} share outputs -> xor-reduce 8 then 16
    #pragma unroll
    for (int op = 0; op < 4; op++) {
        s0[op] = addf2(s0[op], __shfl_xor_sync(0xffffffffu, s0[op], 8));
        q0[op] = addf2(q0[op], __shfl_xor_sync(0xffffffffu, q0[op], 8));
        s1[op] = addf2(s1[op], __shfl_xor_sync(0xffffffffu, s1[op], 8));
        q1[op] = addf2(q1[op], __shfl_xor_sync(0xffffffffu, q1[op], 8));
        s0[op] = addf2(s0[op], __shfl_xor_sync(0xffffffffu, s0[op], 16));
        q0[op] = addf2(q0[op], __shfl_xor_sync(0xffffffffu, q0[op], 16));
        s1[op] = addf2(s1[op], __shfl_xor_sync(0xffffffffu, s1[op], 16));
        q1[op] = addf2(q1[op], __shfl_xor_sync(0xffffffffu, q1[op], 16));
    }

    float* red = Wsm;                      // 8 warps x 256 floats = 8KB
    int w = t >> 5;
    if ((t & 31) < 8) {
        float* rr = &red[w * 256 + (t & 7) * 32];
        #pragma unroll
        for (int op = 0; op < 4; op++) {
            float2 v;
            v = unpk(s0[op]); rr[0  + 2*op] = v.x; rr[1  + 2*op] = v.y;
            v = unpk(q0[op]); rr[8  + 2*op] = v.x; rr[9  + 2*op] = v.y;
            v = unpk(s1[op]); rr[16 + 2*op] = v.x; rr[17 + 2*op] = v.y;
            v = unpk(q1[op]); rr[24 + 2*op] = v.x; rr[25 + 2*op] = v.y;
        }
    }
    __syncthreads();

    {
        int ss = t;                        // 256 sums, one per thread
        float v = 0.f;
        #pragma unroll
        for (int ww = 0; ww < 8; ww++) v += red[ww * 256 + ss];
        int ogl  = ss >> 5;
        int idx  = ss & 31;
        int o    = (ogl << 3) + (idx & 7);
        int isq  = (idx >> 3) & 1;
        int bsel = (idx >> 4) & 1;
        int chan = bsel * 64 + o;
        if (isq) atomicAdd(&d_sq[chan], v);
        else     atomicAdd(&d_sum[chan], v);
    }
}

// -------- kC: instance norm + leaky + transpose to (B,C,H,W) (+ reset cnt) --
__global__ void kC(float* __restrict__ out) {
    __shared__ float tile[8][32][33];
    int t = threadIdx.x;
    int w = t >> 5, lane = t & 31;
    int p0    = blockIdx.x * 128;          // 128 pixels per block (single batch)
    int b     = p0 >> 14;
    int hw0   = p0 & (HW - 1);
    int c0    = (w & 1) * 32;
    int pbase = (w >> 1) * 32;

    int chan   = b * 64 + c0 + lane;
    float mean = d_sum[chan] * (1.0f / 16384.0f);
    float var  = d_sq[chan] * (1.0f / 16384.0f) - mean * mean;
    float rstd = rsqrtf(var + 1e-5f);

    #pragma unroll
    for (int r = 0; r < 32; r++) {
        float v = d_ysc[(size_t)(p0 + pbase + r) * 64 + c0 + lane];
        v = (v - mean) * rstd;
        v = v >= 0.f ? v : 0.01f * v;
        tile[w][r][lane] = v;
    }
    __syncwarp();
    #pragma unroll
    for (int r = 0; r < 32; r++) {
        out[(size_t)(b * 64 + c0 + r) * HW + hw0 + pbase + lane] = tile[w][lane][r];
    }

    // reset routing counters for the next graph replay (kC always runs last)
    if (blockIdx.x == 0 && t < NCLS) d_cnt[t] = 0;
}

extern "C" void kernel_launch(void* const* d_in, const int* in_sizes, int n_in,
                              void* d_out, int out_size) {
    const float* x      = (const float*)d_in[0];
    const float* layout = (const float*)d_in[1];
    const float* pr     = (const float*)d_in[2];
    const float* conv_w = (const float*)d_in[3];
    const float* conv_b = (const float*)d_in[4];
    const float* Wt     = (const float*)d_in[5];
    const float* bt     = (const float*)d_in[6];
    const float* pl     = (const float*)d_in[7];
    float* out = (float*)d_out;

    kA<<<256, 128>>>(x, layout, pr, conv_w, conv_b, pl);
    kA2<<<1, 64>>>();
    kB<<<291, 256>>>(Wt, bt);   // 291 >= max total (class,128-chunk) blocks
    kC<<<256, 256>>>(out);
}

// round 8
// speedup vs baseline: 1.1512x; 1.0418x over previous
#include <cuda_runtime.h>

#define HW   16384      // 128*128
#define NPIX 32768      // B * HW
#define NCLS 35

// -------- device scratch (no allocs allowed) --------
__device__ int   d_cnt[NCLS];              // zero-init at load; re-zeroed by kC
__device__ int   d_prefix[NCLS + 1];
__device__ int   d_clist[NCLS * NPIX];     // 4.6 MB
__device__ float d_xt[NPIX * 64];          // x' pixel-major, 8.4 MB
__device__ float d_ysc[NPIX * 64];         // y  pixel-major, 8.4 MB
__device__ float d_sum[128];
__device__ float d_sq[128];

// -------- packed f32x2 helpers (Blackwell FFMA2 — only via PTX) --------
__device__ __forceinline__ unsigned long long ffma2(unsigned long long a,
                                                    unsigned long long b,
                                                    unsigned long long c) {
    unsigned long long d;
    asm("fma.rn.f32x2 %0, %1, %2, %3;" : "=l"(d) : "l"(a), "l"(b), "l"(c));
    return d;
}
__device__ __forceinline__ unsigned long long addf2(unsigned long long a,
                                                    unsigned long long b) {
    unsigned long long d;
    asm("add.rn.f32x2 %0, %1, %2;" : "=l"(d) : "l"(a), "l"(b));
    return d;
}
__device__ __forceinline__ unsigned long long bcast2(float x) {
    unsigned long long d;
    unsigned xi = __float_as_uint(x);
    asm("mov.b64 %0, {%1, %1};" : "=l"(d) : "r"(xi));
    return d;
}
__device__ __forceinline__ float2 unpk(unsigned long long v) {
    float lo, hi;
    asm("mov.b64 {%0, %1}, %2;" : "=f"(lo), "=f"(hi) : "l"(v));
    return make_float2(lo, hi);
}

// -------- kA: routing + pos-scalar + transpose x'  (512 blk x 256 thr) ------
__global__ void __launch_bounds__(256)
kA(const float* __restrict__ x, const float* __restrict__ layout,
   const float* __restrict__ pr, const float* __restrict__ conv_w,
   const float* __restrict__ conv_b, const float* __restrict__ pl) {
    __shared__ float tile[64 * 65];
    __shared__ float ssm[64];
    int t  = threadIdx.x;
    if (blockIdx.x == 0 && t < 128) { d_sum[t] = 0.f; d_sq[t] = 0.f; }

    int p0 = blockIdx.x * 64;           // 64 pixels per block, single batch
    int b  = p0 >> 14;

    // phase 1: threads 0..63 do pos-scalar + argmax routing for one pixel each
    if (t < 64) {
        int p  = p0 + t;
        int hw = p & (HW - 1);
        int i  = hw >> 7;      // row
        int j  = hw & 127;     // col

        float px = (float)i * (2.0f / 128.0f) - 1.0f;
        float py = (float)j * (2.0f / 128.0f) - 1.0f;
        float pl0 = pl[hw], pl1 = pl[HW + hw];
        const float* prb = pr + b * 2 * HW;
        float pr0 = prb[hw], pr1 = prb[HW + hw];
        const float A23 = 2.0943951023931953f;   // 2*pi/3
        float ax = A23 * (float)(j % 3);
        float ay = A23 * (float)(i % 3);
        float s = px * conv_w[0] + py * conv_w[1] + pl0 * conv_w[2] + pl1 * conv_w[3]
                + pr0 * conv_w[4] + pr1 * conv_w[5]
                + cosf(ax) * conv_w[6] + sinf(ax) * conv_w[7]
                + cosf(ay) * conv_w[8] + sinf(ay) * conv_w[9] + conv_b[0];
        ssm[t] = s;

        // argmax over 35 layout channels (first-max on ties: strict >)
        const float* lb = layout + (size_t)b * NCLS * HW + hw;
        float best = lb[0];
        int arg = 0;
        #pragma unroll
        for (int k = 1; k < NCLS; k++) {
            float v = lb[(size_t)k * HW];
            if (v > best) { best = v; arg = k; }
        }
        int slot = atomicAdd(&d_cnt[arg], 1);
        d_clist[arg * NPIX + slot] = p;
    }
    __syncthreads();

    // phase 2: all 256 threads load x (16 channels per thread) + add s
    {
        int pxl = t >> 2;                 // 0..63 local pixel
        int cg  = (t & 3) << 4;           // channel group base: 0,16,32,48
        int hw  = (p0 + pxl) & (HW - 1);
        const float* xb = x + (size_t)b * 64 * HW + hw;
        float s = ssm[pxl];
        #pragma unroll
        for (int cc = 0; cc < 16; cc++)
            tile[pxl * 65 + cg + cc] = xb[(size_t)(cg + cc) * HW] + s;
    }
    __syncthreads();

    // phase 3: write pixel-major float4 rows
    #pragma unroll
    for (int r = 0; r < 4; r++) {
        int lin = r * 256 + t;
        int pp  = lin >> 4;
        int c4  = (lin & 15) << 2;
        float4 v;
        v.x = tile[pp * 65 + c4 + 0];
        v.y = tile[pp * 65 + c4 + 1];
        v.z = tile[pp * 65 + c4 + 2];
        v.w = tile[pp * 65 + c4 + 3];
        *(float4*)&d_xt[(size_t)(p0 + pp) * 64 + c4] = v;
    }
}

// -------- kA2: parallel scan of per-class block counts (128-px chunks) ------
__global__ void kA2() {
    __shared__ int sc[64];
    int t = threadIdx.x;    // 64 threads
    int v = (t < NCLS) ? ((d_cnt[t] + 127) >> 7) : 0;
    sc[t] = v;
    __syncthreads();
    #pragma unroll
    for (int off = 1; off < 64; off <<= 1) {
        int u = (t >= off) ? sc[t - off] : 0;
        __syncthreads();
        sc[t] += u;
        __syncthreads();
    }
    if (t == 0) d_prefix[0] = 0;
    if (t < NCLS) d_prefix[t + 1] = sc[t];   // inclusive -> prefix[k+1]
}

// -------- kB: grouped GEMM, 128px/block, 256 thr, 4x8 f32x2 tile ------------
__global__ void __launch_bounds__(256, 2)
kB(const float* __restrict__ Wt, const float* __restrict__ bt) {
    __shared__ float Wsm[64 * 64];     // 16KB; aliased as reduction buf after GEMM
    __shared__ float xs[128 * 64];     // 32KB, pixel-major, xor-swizzled

    int t   = threadIdx.x;
    int bid = blockIdx.x;
    if (bid >= d_prefix[NCLS]) return;

    // per-thread binary search: largest k with prefix[k] <= bid (uniform)
    int lo = 0, hi = NCLS;
    #pragma unroll
    for (int it = 0; it < 6; it++) {
        int mid = (lo + hi) >> 1;
        if (d_prefix[mid] <= bid) lo = mid; else hi = mid;
    }
    int k    = lo;
    int base = (bid - d_prefix[k]) << 7;
    int n    = min(128, d_cnt[k] - base);
    const int* clist = d_clist + k * NPIX + base;

    // load expert matrix (16KB)
    const float4* Wk4  = (const float4*)(Wt + (size_t)k * 4096);
    float4*       Wsm4 = (float4*)Wsm;
    #pragma unroll
    for (int r = 0; r < 4; r++) Wsm4[r * 256 + t] = Wk4[r * 256 + t];

    // gather x' rows, xor-swizzled by pixel (key = (pix>>2)&3)
    float4* xs4 = (float4*)xs;
    #pragma unroll
    for (int r = 0; r < 8; r++) {
        int lin = r * 256 + t;
        int pp  = lin >> 4;
        int c4  = lin & 15;
        float4 v = make_float4(0.f, 0.f, 0.f, 0.f);
        if (pp < n) {
            int pix = clist[pp];
            v = ((const float4*)d_xt)[(size_t)pix * 16 + c4];
        }
        xs4[pp * 16 + (c4 ^ ((pp >> 2) & 3))] = v;
    }
    __syncthreads();

    int og8 = (t & 7) << 3;     // 8 outputs = 4 f32x2 pairs
    int pg4 = (t >> 3) << 2;    // 4 pixels
    int key = (t >> 3) & 3;     // swizzle key for this pixel quad

    // acc init = bias (LDG from bt, L2-hot)
    unsigned long long acc[4][4];
    {
        const unsigned long long* bb =
            (const unsigned long long*)(bt + k * 64 + og8);
        unsigned long long b0 = bb[0], b1 = bb[1], b2 = bb[2], b3 = bb[3];
        #pragma unroll
        for (int pp = 0; pp < 4; pp++) {
            acc[pp][0] = b0; acc[pp][1] = b1; acc[pp][2] = b2; acc[pp][3] = b3;
        }
    }

    #pragma unroll 4
    for (int c4 = 0; c4 < 16; c4++) {
        unsigned long long w[4][4];
        #pragma unroll
        for (int kk = 0; kk < 4; kk++) {
            const ulonglong2* wrow = (const ulonglong2*)&Wsm[(c4 * 4 + kk) * 64 + og8];
            ulonglong2 wa = wrow[0];
            ulonglong2 wb = wrow[1];
            w[kk][0] = wa.x; w[kk][1] = wa.y; w[kk][2] = wb.x; w[kk][3] = wb.y;
        }
        int slot = c4 ^ key;
        #pragma unroll
        for (int pp = 0; pp < 4; pp++) {
            float4 xv = xs4[(pg4 + pp) * 16 + slot];
            unsigned long long x0 = bcast2(xv.x);
            unsigned long long x1 = bcast2(xv.y);
            unsigned long long x2 = bcast2(xv.z);
            unsigned long long x3 = bcast2(xv.w);
            #pragma unroll
            for (int op = 0; op < 4; op++) {
                unsigned long long a = acc[pp][op];
                a = ffma2(x0, w[0][op], a);
                a = ffma2(x1, w[1][op], a);
                a = ffma2(x2, w[2][op], a);
                a = ffma2(x3, w[3][op], a);
                acc[pp][op] = a;
            }
        }
    }

    __syncthreads();   // Wsm reads done; safe to alias as reduction buffer

    // write y + accumulate per-(batch,output) moments as f32x2
    unsigned long long s0[4] = {0,0,0,0}, q0[4] = {0,0,0,0};
    unsigned long long s1[4] = {0,0,0,0}, q1[4] = {0,0,0,0};
    #pragma unroll
    for (int pp = 0; pp < 4; pp++) {
        if (pg4 + pp < n) {
            int pix = clist[pg4 + pp];
            float2 y0 = unpk(acc[pp][0]);
            float2 y1 = unpk(acc[pp][1]);
            float2 y2 = unpk(acc[pp][2]);
            float2 y3 = unpk(acc[pp][3]);
            float4* dst = (float4*)&d_ysc[(size_t)pix * 64 + og8];
            dst[0] = make_float4(y0.x, y0.y, y1.x, y1.y);
            dst[1] = make_float4(y2.x, y2.y, y3.x, y3.y);
            if (pix < HW) {
                #pragma unroll
                for (int op = 0; op < 4; op++) {
                    s0[op] = addf2(s0[op], acc[pp][op]);
                    q0[op] = ffma2(acc[pp][op], acc[pp][op], q0[op]);
                }
            } else {
                #pragma unroll
                for (int op = 0; op < 4; op++) {
                    s1[op] = addf2(s1[op], acc[pp][op]);
                    q1[op] = ffma2(acc[pp][op], acc[pp][op], q1[op]);
                }
            }
        }
    }

    // lanes {og, og+8, og+16, og+24} share outputs -> xor-reduce 8 then 16
    #pragma unroll
    for (int op = 0; op < 4; op++) {
        s0[op] = addf2(s0[op], __shfl_xor_sync(0xffffffffu, s0[op], 8));
        q0[op] = addf2(q0[op], __shfl_xor_sync(0xffffffffu, q0[op], 8));
        s1[op] = addf2(s1[op], __shfl_xor_sync(0xffffffffu, s1[op], 8));
        q1[op] = addf2(q1[op], __shfl_xor_sync(0xffffffffu, q1[op], 8));
        s0[op] = addf2(s0[op], __shfl_xor_sync(0xffffffffu, s0[op], 16));
        q0[op] = addf2(q0[op], __shfl_xor_sync(0xffffffffu, q0[op], 16));
        s1[op] = addf2(s1[op], __shfl_xor_sync(0xffffffffu, s1[op], 16));
        q1[op] = addf2(q1[op], __shfl_xor_sync(0xffffffffu, q1[op], 16));
    }

    float* red = Wsm;                      // 8 warps x 256 floats = 8KB
    int w = t >> 5;
    if ((t & 31) < 8) {
        float* rr = &red[w * 256 + (t & 7) * 32];
        #pragma unroll
        for (int op = 0; op < 4; op++) {
            float2 v;
            v = unpk(s0[op]); rr[0  + 2*op] = v.x; rr[1  + 2*op] = v.y;
            v = unpk(q0[op]); rr[8  + 2*op] = v.x; rr[9  + 2*op] = v.y;
            v = unpk(s1[op]); rr[16 + 2*op] = v.x; rr[17 + 2*op] = v.y;
            v = unpk(q1[op]); rr[24 + 2*op] = v.x; rr[25 + 2*op] = v.y;
        }
    }
    __syncthreads();

    {
        int ss = t;                        // 256 sums, one per thread
        float v = 0.f;
        #pragma unroll
        for (int ww = 0; ww < 8; ww++) v += red[ww * 256 + ss];
        int ogl  = ss >> 5;
        int idx  = ss & 31;
        int o    = (ogl << 3) + (idx & 7);
        int isq  = (idx >> 3) & 1;
        int bsel = (idx >> 4) & 1;
        int chan = bsel * 64 + o;
        if (isq) atomicAdd(&d_sq[chan], v);
        else     atomicAdd(&d_sum[chan], v);
    }
}

// -------- kC: instance norm + leaky + transpose (1024 blk x 256 thr) --------
__global__ void __launch_bounds__(256)
kC(float* __restrict__ out) {
    __shared__ float tile[2][32][33];
    int t = threadIdx.x;
    int w = t >> 5, lane = t & 31;
    int p0  = blockIdx.x * 32;          // 32 pixels per block (single batch)
    int b   = p0 >> 14;
    int hw0 = p0 & (HW - 1);
    int ti  = w & 1;                    // channel half (0..1)
    int rg  = (w >> 1) << 3;            // row base (0,8,16,24)

    int chan   = b * 64 + ti * 32 + lane;
    float mean = d_sum[chan] * (1.0f / 16384.0f);
    float var  = d_sq[chan] * (1.0f / 16384.0f) - mean * mean;
    float rstd = rsqrtf(var + 1e-5f);

    #pragma unroll
    for (int r = 0; r < 8; r++) {
        int row = rg + r;
        float v = d_ysc[(size_t)(p0 + row) * 64 + ti * 32 + lane];
        v = (v - mean) * rstd;
        v = v >= 0.f ? v : 0.01f * v;
        tile[ti][row][lane] = v;
    }
    __syncthreads();
    #pragma unroll
    for (int r = 0; r < 8; r++) {
        int ch = ti * 32 + rg + r;
        out[(size_t)(b * 64 + ch) * HW + hw0 + lane] = tile[ti][lane][rg + r];
    }

    // reset routing counters for the next graph replay (kC always runs last)
    if (blockIdx.x == 0 && t < NCLS) d_cnt[t] = 0;
}

extern "C" void kernel_launch(void* const* d_in, const int* in_sizes, int n_in,
                              void* d_out, int out_size) {
    const float* x      = (const float*)d_in[0];
    const float* layout = (const float*)d_in[1];
    const float* pr     = (const float*)d_in[2];
    const float* conv_w = (const float*)d_in[3];
    const float* conv_b = (const float*)d_in[4];
    const float* Wt     = (const float*)d_in[5];
    const float* bt     = (const float*)d_in[6];
    const float* pl     = (const float*)d_in[7];
    float* out = (float*)d_out;

    kA<<<512, 256>>>(x, layout, pr, conv_w, conv_b, pl);
    kA2<<<1, 64>>>();
    kB<<<291, 256>>>(Wt, bt);   // 291 >= max total (class,128-chunk) blocks
    kC<<<1024, 256>>>(out);
}